// round 9
// baseline (speedup 1.0000x reference)
#include <cuda_runtime.h>
#include <math.h>

#define NCLS 19
#define BB   8
#define CC   512
#define HW   16384      // 128*128
#define GPB  4          // channels per block
#define THREADS_A 256   // 8 warps: tensor = w&1, local channel = w>>1

// Scratch (single-writer per slot -> deterministic, no float atomics)
__device__ float         g_partial[2][BB][NCLS][CC];  // [tensor][b][class][channel]
__device__ int           g_cnt_part[BB][NCLS];
__device__ float         g_norm[2][NCLS][CC];
__device__ unsigned int  g_lab8[BB][HW / 4];          // packed u8 labels, 4/word
__device__ int           g_arrive;                    // zero-init; reset by last block

// ---------------------------------------------------------------------------
// Kernel P: pack labels int32 -> u8 (4/word) and compute per-class counts.
// ---------------------------------------------------------------------------
__global__ void __launch_bounds__(256) kP(const int* __restrict__ lab) {
    __shared__ int cnt[32];
    const int b   = blockIdx.x;
    const int tid = threadIdx.x;
    if (tid < 32) cnt[tid] = 0;
    __syncthreads();

    const int4* lab4 = (const int4*)(lab + (size_t)b * HW);
    for (int i = tid; i < HW / 4; i += 256) {
        int4 v = lab4[i];
        g_lab8[b][i] = (unsigned int)v.x | ((unsigned int)v.y << 8) |
                       ((unsigned int)v.z << 16) | ((unsigned int)v.w << 24);
        atomicAdd(&cnt[v.x], 1);
        atomicAdd(&cnt[v.y], 1);
        atomicAdd(&cnt[v.z], 1);
        atomicAdd(&cnt[v.w], 1);
    }
    __syncthreads();
    if (tid < NCLS) g_cnt_part[b][tid] = cnt[tid];
}

// ---------------------------------------------------------------------------
// Kernel A (measured fastest layout): streaming segment-sum.
// Block (cg, b): channels [cg*4, cg*4+4) of image b, both tensors.
// Warp w: tensor = w&1, local channel = w>>1. Private accumulator slab
// acc[w][19][32], scalar floats: bank == lane -> conflict-free LDS/STS.
// smem/block = 19456 B -> 8 blocks/SM = 64 warps (full occupancy).
// ---------------------------------------------------------------------------
__global__ void __launch_bounds__(THREADS_A, 8) kA(const float* __restrict__ fs,
                                                   const float* __restrict__ ft) {
    extern __shared__ float acc[];                    // 8*19*32 floats = 19456 B

    const int tid  = threadIdx.x;
    const int lane = tid & 31;
    const int w    = tid >> 5;
    const int cg   = blockIdx.x;
    const int b    = blockIdx.y;

    for (int i = tid; i < 8 * NCLS * 32; i += THREADS_A) acc[i] = 0.0f;
    __syncthreads();

    const int tensor = w & 1;
    const int c      = cg * GPB + (w >> 1);           // w>>1 in 0..3
    const float4* f  = (const float4*)((tensor ? ft : fs) + ((size_t)b * CC + c) * HW);
    const unsigned int* __restrict__ labw = g_lab8[b];
    float* accw = acc + w * NCLS * 32;

    #pragma unroll 4
    for (int i = lane; i < HW / 4; i += 32) {
        unsigned int l = __ldg(labw + i);
        float4 v = f[i];
        accw[((l      ) & 0xFFu) * 32 + lane] += v.x;
        accw[((l >>  8) & 0xFFu) * 32 + lane] += v.y;
        accw[((l >> 16) & 0xFFu) * 32 + lane] += v.z;
        accw[((l >> 24)        ) * 32 + lane] += v.w;
    }
    __syncwarp();

    // flush: each warp reduces its own [19][32] slab
    for (int k = 0; k < NCLS; k++) {
        float v = accw[k * 32 + lane];
        #pragma unroll
        for (int o = 16; o; o >>= 1) v += __shfl_down_sync(0xFFFFFFFFu, v, o);
        if (lane == 0) g_partial[tensor][b][k][c] = v;
    }
}

// ---------------------------------------------------------------------------
// Kernel C (fused): grid 38, 640 threads.
// Phase 1: block = (tensor s, class k): mean + L2-normalize -> g_norm.
// Phase 2: threadfence-reduction arrival; LAST block resets the counter
// (graph-replay safe), stages g_norm to smem, computes logits (float4 smem
// dots, 4 independent FMA chains), logsumexp, masked-mean loss.
// ---------------------------------------------------------------------------
__global__ void __launch_bounds__(640) kC(float* __restrict__ out) {
    extern __shared__ float nrm[];        // [2][NCLS][CC] floats (77824 B)
    __shared__ float wss[20];
    __shared__ float sh_misc[2];          // denom, inv_norm
    __shared__ int   sh_old;
    __shared__ float sh_log[NCLS][NCLS];
    __shared__ int   sh_cnt[NCLS];
    __shared__ float sh_pc[NCLS];

    const int tid  = threadIdx.x;
    const int lane = tid & 31;
    const int w    = tid >> 5;
    const int task = blockIdx.x;
    const int s    = task >= NCLS ? 1 : 0;
    const int k    = task >= NCLS ? task - NCLS : task;

    // ---- phase 1: normalize this block's (s, k) row -----------------------
    if (tid == 0) {
        int c = 0;
        #pragma unroll
        for (int b = 0; b < BB; b++) c += g_cnt_part[b][k];
        sh_misc[0] = fmaxf((float)c, 1.0f);
    }
    __syncthreads();

    float mean = 0.0f;
    if (tid < CC) {
        float sum = 0.0f;
        #pragma unroll
        for (int b = 0; b < BB; b++) sum += g_partial[s][b][k][tid];
        mean = sum / sh_misc[0];
    }
    float ss = mean * mean;
    #pragma unroll
    for (int o = 16; o; o >>= 1) ss += __shfl_xor_sync(0xFFFFFFFFu, ss, o);
    if (lane == 0) wss[w] = ss;
    __syncthreads();
    if (tid == 0) {
        float tot = 0.0f;
        #pragma unroll
        for (int i = 0; i < 20; i++) tot += wss[i];
        sh_misc[1] = 1.0f / fmaxf(sqrtf(tot), 1e-12f);
    }
    __syncthreads();
    if (tid < CC) g_norm[s][k][tid] = mean * sh_misc[1];

    // ---- phase 2: arrival; last block runs the epilogue -------------------
    __threadfence();                       // release our g_norm row
    __syncthreads();
    if (tid == 0) sh_old = atomicAdd(&g_arrive, 1);
    __syncthreads();
    if (sh_old != 2 * NCLS - 1) return;

    if (tid == 0) g_arrive = 0;            // reset for next graph replay
    __threadfence();                       // acquire all g_norm rows

    // stage both normalized matrices into smem (coalesced)
    {
        const float4* src = (const float4*)&g_norm[0][0][0];
        float4*       dst = (float4*)nrm;
        for (int i = tid; i < 2 * NCLS * CC / 4; i += 640) dst[i] = src[i];
    }
    if (tid < NCLS) {
        int c = 0;
        #pragma unroll
        for (int b = 0; b < BB; b++) c += g_cnt_part[b][tid];
        sh_cnt[tid] = c;
    }
    __syncthreads();

    if (w < NCLS) {                        // warp w -> logits row w
        const float4* si = (const float4*)&nrm[(size_t)w * CC];
        float4 sreg[4];
        #pragma unroll
        for (int q = 0; q < 4; q++) sreg[q] = si[q * 32 + lane];

        for (int j = 0; j < NCLS; j++) {
            const float4* tj = (const float4*)&nrm[(size_t)(NCLS + j) * CC];
            float px = 0.f, py = 0.f, pz = 0.f, pw = 0.f;
            #pragma unroll
            for (int q = 0; q < 4; q++) {
                float4 t = tj[q * 32 + lane];
                px += sreg[q].x * t.x;
                py += sreg[q].y * t.y;
                pz += sreg[q].z * t.z;
                pw += sreg[q].w * t.w;
            }
            float p = (px + py) + (pz + pw);
            #pragma unroll
            for (int o = 16; o; o >>= 1) p += __shfl_down_sync(0xFFFFFFFFu, p, o);
            if (lane == 0) sh_log[w][j] = p * 10.0f;    // / TEMP (0.1)
        }
    }
    __syncthreads();

    if (tid < NCLS) {
        float mx = -1e30f;
        for (int j = 0; j < NCLS; j++) mx = fmaxf(mx, sh_log[tid][j]);
        float sm = 0.0f;
        for (int j = 0; j < NCLS; j++) sm += expf(sh_log[tid][j] - mx);
        float lse = mx + logf(sm);
        sh_pc[tid] = sh_log[tid][tid] - lse;
    }
    __syncthreads();

    if (tid == 0) {
        float sum = 0.0f;
        int np = 0;
        for (int kk = 0; kk < NCLS; kk++)
            if (sh_cnt[kk] > 0) { sum += sh_pc[kk]; np++; }
        out[0] = -sum / (float)np;
    }
}

// ---------------------------------------------------------------------------
extern "C" void kernel_launch(void* const* d_in, const int* in_sizes, int n_in,
                              void* d_out, int out_size) {
    const float* fs  = (const float*)d_in[0];
    const float* ft  = (const float*)d_in[1];
    const int*   lab = (const int*)d_in[2];

    const size_t smemA = (size_t)8 * NCLS * 32 * 4;        // 19456 B
    const size_t smemC = (size_t)2 * NCLS * CC * 4;        // 77824 B
    cudaFuncSetAttribute(kA, cudaFuncAttributeMaxDynamicSharedMemorySize, (int)smemA);
    cudaFuncSetAttribute(kC, cudaFuncAttributeMaxDynamicSharedMemorySize, (int)smemC);

    kP<<<BB, 256>>>(lab);
    kA<<<dim3(CC / GPB, BB), THREADS_A, smemA>>>(fs, ft);
    kC<<<2 * NCLS, 640, smemC>>>((float*)d_out);
}

// round 10
// speedup vs baseline: 1.0750x; 1.0750x over previous
#include <cuda_runtime.h>
#include <math.h>

#define NCLS 19
#define BB   8
#define HW   16384      // 128*128
#define CC   512
#define GPB  4          // channels per kA block
#define THREADS_A 256   // 8 warps: tensor = w&1, local channel = w>>1
#define NSLICE 8        // label-pack slices per image

// Scratch (single-writer per slot -> deterministic, no float atomics)
__device__ float         g_partial[2][BB][NCLS][CC];  // [tensor][b][class][channel]
__device__ int           g_cnt_slot[BB * NSLICE][NCLS]; // per-(image,slice) counts
__device__ float         g_norm[2][NCLS][CC];
__device__ unsigned int  g_lab8[BB][HW / 4];          // packed u8 labels, 4/word
__device__ int           g_arrive;                    // zero-init; reset by last block

// ---------------------------------------------------------------------------
// Kernel P: pack labels int32 -> u8 (4/word) + per-slice class counts.
// Grid (NSLICE, BB): 64 blocks. Each block: 512 words. Single-writer count
// slots -> deterministic, no global atomics, no replay reset needed.
// ---------------------------------------------------------------------------
__global__ void __launch_bounds__(256) kP(const int* __restrict__ lab) {
    __shared__ int cnt[32];
    const int sl  = blockIdx.x;
    const int b   = blockIdx.y;
    const int tid = threadIdx.x;
    if (tid < 32) cnt[tid] = 0;
    __syncthreads();

    const int W = HW / 4 / NSLICE;        // 512 words per slice
    const int base = sl * W;
    const int4* lab4 = (const int4*)(lab + (size_t)b * HW);
    for (int i = tid; i < W; i += 256) {
        int4 v = lab4[base + i];
        g_lab8[b][base + i] = (unsigned int)v.x | ((unsigned int)v.y << 8) |
                              ((unsigned int)v.z << 16) | ((unsigned int)v.w << 24);
        atomicAdd(&cnt[v.x], 1);
        atomicAdd(&cnt[v.y], 1);
        atomicAdd(&cnt[v.z], 1);
        atomicAdd(&cnt[v.w], 1);
    }
    __syncthreads();
    if (tid < NCLS) g_cnt_slot[b * NSLICE + sl][tid] = cnt[tid];
}

// ---------------------------------------------------------------------------
// Kernel A (measured fastest layout): streaming segment-sum.
// Block (cg, b): channels [cg*4, cg*4+4) of image b, both tensors.
// Warp w: tensor = w&1, local channel = w>>1. Private accumulator slab
// acc[w][19][32], scalar floats: bank == lane -> conflict-free LDS/STS.
// smem/block = 19456 B -> 8 blocks/SM = 64 warps (full occupancy).
// ---------------------------------------------------------------------------
__global__ void __launch_bounds__(THREADS_A, 8) kA(const float* __restrict__ fs,
                                                   const float* __restrict__ ft) {
    extern __shared__ float acc[];                    // 8*19*32 floats = 19456 B

    const int tid  = threadIdx.x;
    const int lane = tid & 31;
    const int w    = tid >> 5;
    const int cg   = blockIdx.x;
    const int b    = blockIdx.y;

    for (int i = tid; i < 8 * NCLS * 32; i += THREADS_A) acc[i] = 0.0f;
    __syncthreads();

    const int tensor = w & 1;
    const int c      = cg * GPB + (w >> 1);           // w>>1 in 0..3
    const float4* f  = (const float4*)((tensor ? ft : fs) + ((size_t)b * CC + c) * HW);
    const unsigned int* __restrict__ labw = g_lab8[b];
    float* accw = acc + w * NCLS * 32;

    #pragma unroll 4
    for (int i = lane; i < HW / 4; i += 32) {
        unsigned int l = __ldg(labw + i);
        float4 v = f[i];
        accw[((l      ) & 0xFFu) * 32 + lane] += v.x;
        accw[((l >>  8) & 0xFFu) * 32 + lane] += v.y;
        accw[((l >> 16) & 0xFFu) * 32 + lane] += v.z;
        accw[((l >> 24)        ) * 32 + lane] += v.w;
    }
    __syncwarp();

    // flush: each warp reduces its own [19][32] slab
    for (int k = 0; k < NCLS; k++) {
        float v = accw[k * 32 + lane];
        #pragma unroll
        for (int o = 16; o; o >>= 1) v += __shfl_down_sync(0xFFFFFFFFu, v, o);
        if (lane == 0) g_partial[tensor][b][k][c] = v;
    }
}

// ---------------------------------------------------------------------------
// Kernel C (fused): grid 38, 640 threads.
// Phase 1: block = (tensor s, class k): mean + L2-normalize -> g_norm.
// Phase 2: threadfence-reduction arrival; LAST block resets the counter
// (graph-replay safe), stages g_norm to smem, computes logits (float4 smem
// dots, 4 independent FMA chains), logsumexp, masked-mean loss.
// ---------------------------------------------------------------------------
__global__ void __launch_bounds__(640) kC(float* __restrict__ out) {
    extern __shared__ float nrm[];        // [2][NCLS][CC] floats (77824 B)
    __shared__ float wss[20];
    __shared__ float sh_misc[2];          // denom, inv_norm
    __shared__ int   sh_old;
    __shared__ float sh_log[NCLS][NCLS];
    __shared__ int   sh_cnt[NCLS];
    __shared__ float sh_pc[NCLS];

    const int tid  = threadIdx.x;
    const int lane = tid & 31;
    const int w    = tid >> 5;
    const int task = blockIdx.x;
    const int s    = task >= NCLS ? 1 : 0;
    const int k    = task >= NCLS ? task - NCLS : task;

    // ---- phase 1: normalize this block's (s, k) row -----------------------
    if (w == 0) {                          // lane-parallel count sum (64 slots)
        int c = g_cnt_slot[lane][k] + g_cnt_slot[lane + 32][k];
        #pragma unroll
        for (int o = 16; o; o >>= 1) c += __shfl_down_sync(0xFFFFFFFFu, c, o);
        if (lane == 0) sh_misc[0] = fmaxf((float)c, 1.0f);
    }
    __syncthreads();

    float mean = 0.0f;
    if (tid < CC) {
        float sum = 0.0f;
        #pragma unroll
        for (int b = 0; b < BB; b++) sum += g_partial[s][b][k][tid];
        mean = sum / sh_misc[0];
    }
    float ss = mean * mean;
    #pragma unroll
    for (int o = 16; o; o >>= 1) ss += __shfl_xor_sync(0xFFFFFFFFu, ss, o);
    if (lane == 0) wss[w] = ss;
    __syncthreads();
    if (tid == 0) {
        float tot = 0.0f;
        #pragma unroll
        for (int i = 0; i < 20; i++) tot += wss[i];
        sh_misc[1] = 1.0f / fmaxf(sqrtf(tot), 1e-12f);
    }
    __syncthreads();
    if (tid < CC) g_norm[s][k][tid] = mean * sh_misc[1];

    // ---- phase 2: arrival; last block runs the epilogue -------------------
    __threadfence();                       // release our g_norm row
    __syncthreads();
    if (tid == 0) sh_old = atomicAdd(&g_arrive, 1);
    __syncthreads();
    if (sh_old != 2 * NCLS - 1) return;

    if (tid == 0) g_arrive = 0;            // reset for next graph replay
    __threadfence();                       // acquire all g_norm rows

    // stage both normalized matrices into smem (coalesced)
    {
        const float4* src = (const float4*)&g_norm[0][0][0];
        float4*       dst = (float4*)nrm;
        for (int i = tid; i < 2 * NCLS * CC / 4; i += 640) dst[i] = src[i];
    }
    if (w < NCLS) {                        // warp w -> total count for class w
        int c = g_cnt_slot[lane][w] + g_cnt_slot[lane + 32][w];
        #pragma unroll
        for (int o = 16; o; o >>= 1) c += __shfl_down_sync(0xFFFFFFFFu, c, o);
        if (lane == 0) sh_cnt[w] = c;
    }
    __syncthreads();

    if (w < NCLS) {                        // warp w -> logits row w
        const float4* si = (const float4*)&nrm[(size_t)w * CC];
        float4 sreg[4];
        #pragma unroll
        for (int q = 0; q < 4; q++) sreg[q] = si[q * 32 + lane];

        for (int j = 0; j < NCLS; j++) {
            const float4* tj = (const float4*)&nrm[(size_t)(NCLS + j) * CC];
            float px = 0.f, py = 0.f, pz = 0.f, pw = 0.f;
            #pragma unroll
            for (int q = 0; q < 4; q++) {
                float4 t = tj[q * 32 + lane];
                px += sreg[q].x * t.x;
                py += sreg[q].y * t.y;
                pz += sreg[q].z * t.z;
                pw += sreg[q].w * t.w;
            }
            float p = (px + py) + (pz + pw);
            #pragma unroll
            for (int o = 16; o; o >>= 1) p += __shfl_down_sync(0xFFFFFFFFu, p, o);
            if (lane == 0) sh_log[w][j] = p * 10.0f;    // / TEMP (0.1)
        }
    }
    __syncthreads();

    if (tid < NCLS) {
        float mx = -1e30f;
        for (int j = 0; j < NCLS; j++) mx = fmaxf(mx, sh_log[tid][j]);
        float sm = 0.0f;
        for (int j = 0; j < NCLS; j++) sm += expf(sh_log[tid][j] - mx);
        float lse = mx + logf(sm);
        sh_pc[tid] = sh_log[tid][tid] - lse;
    }
    __syncthreads();

    if (tid == 0) {
        float sum = 0.0f;
        int np = 0;
        for (int kk = 0; kk < NCLS; kk++)
            if (sh_cnt[kk] > 0) { sum += sh_pc[kk]; np++; }
        out[0] = -sum / (float)np;
    }
}

// ---------------------------------------------------------------------------
extern "C" void kernel_launch(void* const* d_in, const int* in_sizes, int n_in,
                              void* d_out, int out_size) {
    const float* fs  = (const float*)d_in[0];
    const float* ft  = (const float*)d_in[1];
    const int*   lab = (const int*)d_in[2];

    const size_t smemA = (size_t)8 * NCLS * 32 * 4;        // 19456 B
    const size_t smemC = (size_t)2 * NCLS * CC * 4;        // 77824 B
    cudaFuncSetAttribute(kA, cudaFuncAttributeMaxDynamicSharedMemorySize, (int)smemA);
    cudaFuncSetAttribute(kC, cudaFuncAttributeMaxDynamicSharedMemorySize, (int)smemC);

    kP<<<dim3(NSLICE, BB), 256>>>(lab);
    kA<<<dim3(CC / GPB, BB), THREADS_A, smemA>>>(fs, ft);
    kC<<<2 * NCLS, 640, smemC>>>((float*)d_out);
}

// round 11
// speedup vs baseline: 1.1781x; 1.0960x over previous
#include <cuda_runtime.h>
#include <math.h>

#define NCLS 19
#define BB   8
#define HW   16384      // 128*128
#define CC   512
#define GPB  4          // channels per kA block
#define THREADS_A 256   // 8 warps: tensor = w&1, local channel = w>>1
#define NSLICE 32       // label-pack slices per image

// Scratch (single-writer per slot -> deterministic, no float atomics)
__device__ float         g_partial[2][BB][NCLS][CC];    // [tensor][b][class][channel]
__device__ int           g_cnt_slot[BB * NSLICE][NCLS]; // per-(image,slice) counts
__device__ float         g_norm[2][NCLS][CC];
__device__ unsigned int  g_lab8[BB][HW / 4];            // packed u8 labels, 4/word
__device__ int           g_arrive;                      // zero-init; reset by last block

// ---------------------------------------------------------------------------
// Kernel P: pack labels int32 -> u8 (4/word) + per-slice class counts.
// Grid (NSLICE, BB) = 256 blocks x 128 threads, 1 word/thread. Single-writer
// count slots -> deterministic, no global atomics, no replay reset needed.
// ---------------------------------------------------------------------------
__global__ void __launch_bounds__(128) kP(const int* __restrict__ lab) {
    __shared__ int cnt[32];
    const int sl  = blockIdx.x;
    const int b   = blockIdx.y;
    const int tid = threadIdx.x;
    if (tid < 32) cnt[tid] = 0;
    __syncthreads();

    const int W = HW / 4 / NSLICE;        // 128 words per slice
    const int i = sl * W + tid;           // 128 threads == W
    int4 v = ((const int4*)(lab + (size_t)b * HW))[i];
    g_lab8[b][i] = (unsigned int)v.x | ((unsigned int)v.y << 8) |
                   ((unsigned int)v.z << 16) | ((unsigned int)v.w << 24);
    atomicAdd(&cnt[v.x], 1);
    atomicAdd(&cnt[v.y], 1);
    atomicAdd(&cnt[v.z], 1);
    atomicAdd(&cnt[v.w], 1);
    __syncthreads();
    if (tid < NCLS) g_cnt_slot[b * NSLICE + sl][tid] = cnt[tid];
}

// ---------------------------------------------------------------------------
// Kernel A: streaming segment-sum (measured-best layout + explicit prefetch).
// Block (cg, b): channels [cg*4, cg*4+4) of image b, both tensors.
// Warp w: tensor = w&1, local channel = w>>1. Private accumulator slab
// acc[w][19][32], scalar floats: bank == lane -> conflict-free LDS/STS.
// smem/block = 19456 B -> 8 blocks/SM = 64 warps (full occupancy).
// PDL: grid-dependency sync AFTER smem zeroing (overlaps kP tail).
// ---------------------------------------------------------------------------
__global__ void __launch_bounds__(THREADS_A, 8) kA(const float* __restrict__ fs,
                                                   const float* __restrict__ ft) {
    extern __shared__ float acc[];                    // 8*19*32 floats = 19456 B

    const int tid  = threadIdx.x;
    const int lane = tid & 31;
    const int w    = tid >> 5;
    const int cg   = blockIdx.x;
    const int b    = blockIdx.y;

    for (int i = tid; i < 8 * NCLS * 32; i += THREADS_A) acc[i] = 0.0f;

    cudaGridDependencySynchronize();      // wait for kP (PDL edge)
    __syncthreads();

    const int tensor = w & 1;
    const int c      = cg * GPB + (w >> 1);           // w>>1 in 0..3
    const float4* f  = (const float4*)((tensor ? ft : fs) + ((size_t)b * CC + c) * HW);
    const unsigned int* __restrict__ labw = g_lab8[b];
    float* accw = acc + w * NCLS * 32;

    // explicit 1-deep prefetch: next (label, float4) issued before current RMWs
    unsigned int l = __ldg(labw + lane);
    float4 v = f[lane];
    #pragma unroll 2
    for (int ii = lane + 32; ii < HW / 4; ii += 32) {
        unsigned int nl = __ldg(labw + ii);
        float4 nv = f[ii];
        accw[((l      ) & 0xFFu) * 32 + lane] += v.x;
        accw[((l >>  8) & 0xFFu) * 32 + lane] += v.y;
        accw[((l >> 16) & 0xFFu) * 32 + lane] += v.z;
        accw[((l >> 24)        ) * 32 + lane] += v.w;
        l = nl; v = nv;
    }
    accw[((l      ) & 0xFFu) * 32 + lane] += v.x;
    accw[((l >>  8) & 0xFFu) * 32 + lane] += v.y;
    accw[((l >> 16) & 0xFFu) * 32 + lane] += v.z;
    accw[((l >> 24)        ) * 32 + lane] += v.w;

    cudaTriggerProgrammaticLaunchCompletion();  // let kC begin launching
    __syncwarp();

    // flush: each warp reduces its own [19][32] slab
    for (int k = 0; k < NCLS; k++) {
        float vv = accw[k * 32 + lane];
        #pragma unroll
        for (int o = 16; o; o >>= 1) vv += __shfl_down_sync(0xFFFFFFFFu, vv, o);
        if (lane == 0) g_partial[tensor][b][k][c] = vv;
    }
}

// ---------------------------------------------------------------------------
// Kernel C (fused): grid 38, 640 threads.
// Phase 1: block = (tensor s, class k): mean + L2-normalize -> g_norm.
// Phase 2: threadfence-reduction arrival; LAST block resets the counter
// (graph-replay safe), stages g_norm to smem, computes logits (float4 smem
// dots, 4 independent FMA chains), logsumexp, masked-mean loss.
// ---------------------------------------------------------------------------
__global__ void __launch_bounds__(640) kC(float* __restrict__ out) {
    extern __shared__ float nrm[];        // [2][NCLS][CC] floats (77824 B)
    __shared__ float wss[20];
    __shared__ float sh_misc[2];          // denom, inv_norm
    __shared__ int   sh_old;
    __shared__ float sh_log[NCLS][NCLS];
    __shared__ int   sh_cnt[NCLS];
    __shared__ float sh_pc[NCLS];

    const int tid  = threadIdx.x;
    const int lane = tid & 31;
    const int w    = tid >> 5;
    const int task = blockIdx.x;
    const int s    = task >= NCLS ? 1 : 0;
    const int k    = task >= NCLS ? task - NCLS : task;

    cudaGridDependencySynchronize();      // wait for kA (PDL edge; kP transitive)

    // ---- phase 1: normalize this block's (s, k) row -----------------------
    if (w == 0) {                          // lane-parallel count sum (256 slots)
        int c = 0;
        #pragma unroll
        for (int q = 0; q < BB * NSLICE / 32; q++)
            c += g_cnt_slot[lane + 32 * q][k];
        #pragma unroll
        for (int o = 16; o; o >>= 1) c += __shfl_down_sync(0xFFFFFFFFu, c, o);
        if (lane == 0) sh_misc[0] = fmaxf((float)c, 1.0f);
    }
    __syncthreads();

    float mean = 0.0f;
    if (tid < CC) {
        float sum = 0.0f;
        #pragma unroll
        for (int b = 0; b < BB; b++) sum += g_partial[s][b][k][tid];
        mean = sum / sh_misc[0];
    }
    float ss = mean * mean;
    #pragma unroll
    for (int o = 16; o; o >>= 1) ss += __shfl_xor_sync(0xFFFFFFFFu, ss, o);
    if (lane == 0) wss[w] = ss;
    __syncthreads();
    if (tid == 0) {
        float tot = 0.0f;
        #pragma unroll
        for (int i = 0; i < 20; i++) tot += wss[i];
        sh_misc[1] = 1.0f / fmaxf(sqrtf(tot), 1e-12f);
    }
    __syncthreads();
    if (tid < CC) g_norm[s][k][tid] = mean * sh_misc[1];

    // ---- phase 2: arrival; last block runs the epilogue -------------------
    __threadfence();                       // release our g_norm row
    __syncthreads();
    if (tid == 0) sh_old = atomicAdd(&g_arrive, 1);
    __syncthreads();
    if (sh_old != 2 * NCLS - 1) return;

    if (tid == 0) g_arrive = 0;            // reset for next graph replay
    __threadfence();                       // acquire all g_norm rows

    // stage both normalized matrices into smem (coalesced)
    {
        const float4* src = (const float4*)&g_norm[0][0][0];
        float4*       dst = (float4*)nrm;
        for (int i = tid; i < 2 * NCLS * CC / 4; i += 640) dst[i] = src[i];
    }
    if (w < NCLS) {                        // warp w -> total count for class w
        int c = 0;
        #pragma unroll
        for (int q = 0; q < BB * NSLICE / 32; q++)
            c += g_cnt_slot[lane + 32 * q][w];
        #pragma unroll
        for (int o = 16; o; o >>= 1) c += __shfl_down_sync(0xFFFFFFFFu, c, o);
        if (lane == 0) sh_cnt[w] = c;
    }
    __syncthreads();

    if (w < NCLS) {                        // warp w -> logits row w
        const float4* si = (const float4*)&nrm[(size_t)w * CC];
        float4 sreg[4];
        #pragma unroll
        for (int q = 0; q < 4; q++) sreg[q] = si[q * 32 + lane];

        for (int j = 0; j < NCLS; j++) {
            const float4* tj = (const float4*)&nrm[(size_t)(NCLS + j) * CC];
            float px = 0.f, py = 0.f, pz = 0.f, pw = 0.f;
            #pragma unroll
            for (int q = 0; q < 4; q++) {
                float4 t = tj[q * 32 + lane];
                px += sreg[q].x * t.x;
                py += sreg[q].y * t.y;
                pz += sreg[q].z * t.z;
                pw += sreg[q].w * t.w;
            }
            float p = (px + py) + (pz + pw);
            #pragma unroll
            for (int o = 16; o; o >>= 1) p += __shfl_down_sync(0xFFFFFFFFu, p, o);
            if (lane == 0) sh_log[w][j] = p * 10.0f;    // / TEMP (0.1)
        }
    }
    __syncthreads();

    if (tid < NCLS) {
        float mx = -1e30f;
        for (int j = 0; j < NCLS; j++) mx = fmaxf(mx, sh_log[tid][j]);
        float sm = 0.0f;
        for (int j = 0; j < NCLS; j++) sm += expf(sh_log[tid][j] - mx);
        float lse = mx + logf(sm);
        sh_pc[tid] = sh_log[tid][tid] - lse;
    }
    __syncthreads();

    if (tid == 0) {
        float sum = 0.0f;
        int np = 0;
        for (int kk = 0; kk < NCLS; kk++)
            if (sh_cnt[kk] > 0) { sum += sh_pc[kk]; np++; }
        out[0] = -sum / (float)np;
    }
}

// ---------------------------------------------------------------------------
extern "C" void kernel_launch(void* const* d_in, const int* in_sizes, int n_in,
                              void* d_out, int out_size) {
    const float* fs  = (const float*)d_in[0];
    const float* ft  = (const float*)d_in[1];
    const int*   lab = (const int*)d_in[2];

    const size_t smemA = (size_t)8 * NCLS * 32 * 4;        // 19456 B
    const size_t smemC = (size_t)2 * NCLS * CC * 4;        // 77824 B
    cudaFuncSetAttribute(kA, cudaFuncAttributeMaxDynamicSharedMemorySize, (int)smemA);
    cudaFuncSetAttribute(kC, cudaFuncAttributeMaxDynamicSharedMemorySize, (int)smemC);

    // kP: normal launch
    kP<<<dim3(NSLICE, BB), 128>>>(lab);

    // kA: PDL follower of kP
    {
        cudaLaunchConfig_t cfg = {};
        cfg.gridDim = dim3(CC / GPB, BB);
        cfg.blockDim = dim3(THREADS_A);
        cfg.dynamicSmemBytes = smemA;
        cfg.stream = 0;
        cudaLaunchAttribute at[1];
        at[0].id = cudaLaunchAttributeProgrammaticStreamSerialization;
        at[0].val.programmaticStreamSerializationAllowed = 1;
        cfg.attrs = at;
        cfg.numAttrs = 1;
        cudaLaunchKernelEx(&cfg, kA, fs, ft);
    }

    // kC: PDL follower of kA
    {
        cudaLaunchConfig_t cfg = {};
        cfg.gridDim = dim3(2 * NCLS);
        cfg.blockDim = dim3(640);
        cfg.dynamicSmemBytes = smemC;
        cfg.stream = 0;
        cudaLaunchAttribute at[1];
        at[0].id = cudaLaunchAttributeProgrammaticStreamSerialization;
        at[0].val.programmaticStreamSerializationAllowed = 1;
        cfg.attrs = at;
        cfg.numAttrs = 1;
        cudaLaunchKernelEx(&cfg, kC, (float*)d_out);
    }
}